// round 5
// baseline (speedup 1.0000x reference)
#include <cuda_runtime.h>

#define NN  50000
#define FI  96
#define HID 128
#define FO  64
#define NE  800000

// ---------------- device scratch (no allocations allowed) ----------------
__device__ __align__(16) int   g_src[NE];
__device__ __align__(16) int   g_dst[NE];
__device__ __align__(16) float g_agg1[(size_t)NN * FI];   // 19.2 MB
__device__ __align__(16) float g_h[(size_t)NN * HID];     // 25.6 MB
__device__ __align__(16) float g_p[(size_t)NN * FO];      // 12.8 MB
__device__ int g_is64;

// vectorized fire-and-forget L2 atomic add (sm_90+)
__device__ __forceinline__ void red_add_v4(float4* p, float4 v) {
    asm volatile("red.global.add.v4.f32 [%0], {%1,%2,%3,%4};"
                 :: "l"(p), "f"(v.x), "f"(v.y), "f"(v.z), "f"(v.w)
                 : "memory");
}

// ---------------- dtype detect: int64 edge_index has all-odd-int32-words == 0 ----------------
__global__ void k_detect(const int* __restrict__ ei32) {
    __shared__ int nz;
    if (threadIdx.x == 0) nz = 0;
    __syncthreads();
    // scan odd 32-bit words of the first 256 "int64 slots"
    if (ei32[2 * threadIdx.x + 1] != 0) atomicAdd(&nz, 1);
    __syncthreads();
    if (threadIdx.x == 0) g_is64 = (nz == 0) ? 1 : 0;
}

// ---------------- edge index -> int32, with bounds clamp (invalid -> self-loop) ----------------
__global__ void k_convert(const void* __restrict__ ei) {
    int e = blockIdx.x * blockDim.x + threadIdx.x;
    if (e >= NE) return;
    int s, d;
    if (g_is64) {
        const long long* p = (const long long*)ei;
        s = (int)p[e]; d = (int)p[NE + e];
    } else {
        const int* p = (const int*)ei;
        s = p[e]; d = p[NE + e];
    }
    if (s < 0 || s >= NN || d < 0 || d >= NN) { s = 0; d = 0; }  // skipped as self-loop
    g_src[e] = s;
    g_dst[e] = d;
}

// ---------------- zero agg1 ----------------
__global__ void k_zero_agg1() {
    int i = blockIdx.x * blockDim.x + threadIdx.x;
    const int n4 = NN * FI / 4;  // 1.2M float4
    if (i < n4) ((float4*)g_agg1)[i] = make_float4(0.f, 0.f, 0.f, 0.f);
}

// ---------------- scatter 1: agg1[dst] += x[src], 96 feats, 8 thr/edge ----------------
__global__ void k_scatter1(const float* __restrict__ x) {
    int gid = blockIdx.x * blockDim.x + threadIdx.x;
    int e = gid >> 3;
    int c = gid & 7;
    if (e >= NE) return;
    int s = g_src[e], d = g_dst[e];
    if (s == d) return;                       // remove_self_loops (and clamped-invalid)
    const float4* xs = (const float4*)(x + (size_t)s * FI);
    float4* ad = (float4*)(g_agg1 + (size_t)d * FI);
#pragma unroll
    for (int i = 0; i < 3; i++) {
        red_add_v4(ad + c + 8 * i, xs[c + 8 * i]);
    }
}

// ---------------- gemm1: h = relu(agg1@W1_rel^T + x@W1_root^T + b1) ----------------
// block = 512 thr (16 warps). Each warp covers a full 128-wide output row
// (lane -> float4 of 4 j's) for 4 consecutive nodes at a time.
#define G1_SMEM_FLOATS (12288 + 12288 + 128 + 16 * 768)

__global__ __launch_bounds__(512, 1)
void k_gemm1(const float* __restrict__ x, const float* __restrict__ Wrel,
             const float* __restrict__ b, const float* __restrict__ Wroot) {
    extern __shared__ float sm[];
    float* sWrel  = sm;                 // [96][128] transposed
    float* sWroot = sm + 12288;
    float* sb     = sm + 24576;
    float* stage  = sm + 24704;
    int tid  = threadIdx.x;
    int warp = tid >> 5, lane = tid & 31;

    for (int i = tid; i < 12288; i += 512) {     // transpose-load both W's
        int j = i / FI, k = i - j * FI;          // src = W[j][k]
        sWrel [k * HID + j] = Wrel [i];
        sWroot[k * HID + j] = Wroot[i];
    }
    if (tid < HID) sb[tid] = b[tid];
    __syncthreads();

    float* aggS = stage + warp * 768;
    float* xS   = aggS + 384;
    const float4* wr4 = (const float4*)sWrel;
    const float4* wo4 = (const float4*)sWroot;
    const int ngroups = NN / 4;  // 12500, exact

    for (int g = blockIdx.x * 16 + warp; g < ngroups; g += gridDim.x * 16) {
        int node0 = g * 4;
        __syncwarp();
        const float4* ap = (const float4*)(g_agg1 + (size_t)node0 * FI); // 96 float4
        const float4* xp = (const float4*)(x      + (size_t)node0 * FI);
        float4* aS4 = (float4*)aggS;
        float4* xS4 = (float4*)xS;
#pragma unroll
        for (int i = 0; i < 3; i++) {
            aS4[lane + 32 * i] = ap[lane + 32 * i];
            xS4[lane + 32 * i] = xp[lane + 32 * i];
        }
        __syncwarp();

        float4 acc0 = make_float4(0, 0, 0, 0), acc1 = acc0, acc2 = acc0, acc3 = acc0;
#pragma unroll 4
        for (int k = 0; k < FI; k++) {
            float4 wr = wr4[k * 32 + lane];
            float4 wo = wo4[k * 32 + lane];
            float a0 = aggS[k],       a1 = aggS[96 + k],
                  a2 = aggS[192 + k], a3 = aggS[288 + k];
            float v0 = xS[k],         v1 = xS[96 + k],
                  v2 = xS[192 + k],   v3 = xS[288 + k];
#define UPD1(acc, a, v)                                            \
            acc.x = fmaf(a, wr.x, acc.x); acc.y = fmaf(a, wr.y, acc.y);  \
            acc.z = fmaf(a, wr.z, acc.z); acc.w = fmaf(a, wr.w, acc.w);  \
            acc.x = fmaf(v, wo.x, acc.x); acc.y = fmaf(v, wo.y, acc.y);  \
            acc.z = fmaf(v, wo.z, acc.z); acc.w = fmaf(v, wo.w, acc.w);
            UPD1(acc0, a0, v0)
            UPD1(acc1, a1, v1)
            UPD1(acc2, a2, v2)
            UPD1(acc3, a3, v3)
#undef UPD1
        }
        float4 bb = ((const float4*)sb)[lane];
#define STORE1(acc, nn)                                                          \
        {   float4 r;                                                            \
            r.x = fmaxf(acc.x + bb.x, 0.f); r.y = fmaxf(acc.y + bb.y, 0.f);      \
            r.z = fmaxf(acc.z + bb.z, 0.f); r.w = fmaxf(acc.w + bb.w, 0.f);      \
            ((float4*)(g_h + (size_t)(node0 + nn) * HID))[lane] = r; }
        STORE1(acc0, 0) STORE1(acc1, 1) STORE1(acc2, 2) STORE1(acc3, 3)
#undef STORE1
    }
}

// ---------------- gemm2: p = h@W2_rel^T ; out = h@W2_root^T + b2 ----------------
#define G2_SMEM_FLOATS (8192 + 8192 + 64 + 16 * 512)

__global__ __launch_bounds__(512, 1)
void k_gemm2(const float* __restrict__ Wrel, const float* __restrict__ b,
             const float* __restrict__ Wroot, float* __restrict__ out) {
    extern __shared__ float sm[];
    float* sWrel  = sm;                 // [128][64] transposed
    float* sWroot = sm + 8192;
    float* sb     = sm + 16384;
    float* stage  = sm + 16448;
    int tid  = threadIdx.x;
    int warp = tid >> 5, lane = tid & 31;

    for (int i = tid; i < 8192; i += 512) {
        int j = i >> 7, k = i & 127;     // src = W[j][k], j<64, k<128
        sWrel [k * FO + j] = Wrel [i];
        sWroot[k * FO + j] = Wroot[i];
    }
    if (tid < FO) sb[tid] = b[tid];
    __syncthreads();

    float* hS = stage + warp * 512;
    const float2* wr2 = (const float2*)sWrel;
    const float2* wo2 = (const float2*)sWroot;
    const int ngroups = NN / 4;

    for (int g = blockIdx.x * 16 + warp; g < ngroups; g += gridDim.x * 16) {
        int node0 = g * 4;
        __syncwarp();
        const float4* hp = (const float4*)(g_h + (size_t)node0 * HID); // 128 float4
        float4* hS4 = (float4*)hS;
#pragma unroll
        for (int i = 0; i < 4; i++) hS4[lane + 32 * i] = hp[lane + 32 * i];
        __syncwarp();

        float2 accP[4], accO[4];
#pragma unroll
        for (int nn = 0; nn < 4; nn++) {
            accP[nn] = make_float2(0.f, 0.f);
            accO[nn] = make_float2(0.f, 0.f);
        }
#pragma unroll 4
        for (int k = 0; k < HID; k++) {
            float2 wr = wr2[k * 32 + lane];
            float2 wo = wo2[k * 32 + lane];
#pragma unroll
            for (int nn = 0; nn < 4; nn++) {
                float hv = hS[nn * HID + k];
                accP[nn].x = fmaf(hv, wr.x, accP[nn].x);
                accP[nn].y = fmaf(hv, wr.y, accP[nn].y);
                accO[nn].x = fmaf(hv, wo.x, accO[nn].x);
                accO[nn].y = fmaf(hv, wo.y, accO[nn].y);
            }
        }
        float2 bb = ((const float2*)sb)[lane];
#pragma unroll
        for (int nn = 0; nn < 4; nn++) {
            ((float2*)(g_p + (size_t)(node0 + nn) * FO))[lane] = accP[nn];
            float2 o;
            o.x = accO[nn].x + bb.x;
            o.y = accO[nn].y + bb.y;
            ((float2*)(out + (size_t)(node0 + nn) * FO))[lane] = o;
        }
    }
}

// ---------------- scatter 2: out[dst] += p[src], 64 feats, 16 thr/edge ----------------
__global__ void k_scatter2(float* __restrict__ out) {
    int gid = blockIdx.x * blockDim.x + threadIdx.x;
    int e = gid >> 4;
    int c = gid & 15;
    if (e >= NE) return;
    int s = g_src[e], d = g_dst[e];
    if (s == d) return;
    float4 v = ((const float4*)(g_p + (size_t)s * FO))[c];
    red_add_v4(((float4*)(out + (size_t)d * FO)) + c, v);
}

// ---------------- launch ----------------
extern "C" void kernel_launch(void* const* d_in, const int* in_sizes, int n_in,
                              void* d_out, int out_size) {
    const float* x       = (const float*)d_in[0];
    const void*  ei      = d_in[1];                    // int32 or int64, detected on device
    const float* W1_rel  = (const float*)d_in[2];
    const float* b1      = (const float*)d_in[3];
    const float* W1_root = (const float*)d_in[4];
    const float* W2_rel  = (const float*)d_in[5];
    const float* b2      = (const float*)d_in[6];
    const float* W2_root = (const float*)d_in[7];
    float* out = (float*)d_out;

    const int g1_smem = G1_SMEM_FLOATS * 4;   // 147968 B
    const int g2_smem = G2_SMEM_FLOATS * 4;   //  98560 B
    cudaFuncSetAttribute(k_gemm1, cudaFuncAttributeMaxDynamicSharedMemorySize, g1_smem);
    cudaFuncSetAttribute(k_gemm2, cudaFuncAttributeMaxDynamicSharedMemorySize, g2_smem);

    k_detect<<<1, 256>>>((const int*)ei);
    k_convert<<<(NE + 255) / 256, 256>>>(ei);
    k_zero_agg1<<<(NN * FI / 4 + 255) / 256, 256>>>();
    k_scatter1<<<(NE * 8 + 255) / 256, 256>>>(x);
    k_gemm1<<<148, 512, g1_smem>>>(x, W1_rel, b1, W1_root);
    k_gemm2<<<148, 512, g2_smem>>>(W2_rel, b2, W2_root, out);
    k_scatter2<<<(NE * 16 + 255) / 256, 256>>>(out);
}